// round 15
// baseline (speedup 1.0000x reference)
#include <cuda_runtime.h>
#include <cuda_bf16.h>

#define BB 4
#define TT 512
#define VV 8000
#define HH 7
#define VP 8192          // padded vocab stride
#define GUARD_TH 2e-3f   // fast/limit switch radius
#define TAU_SCALE 2.5e-3f // GUARD_TH * 1.25 margin; tau = TAU_SCALE/(2*pi*|f_v|) via |rcp(b1)|
#define RMAGIC 12582912.0f // 1.5 * 2^23 round-to-nearest-int trick

// Scratch (allocation-free rule: __device__ globals)
__device__ float g_vocab[3][HH][VP];   // [0]=angle, [1]=sqrt2*A/h^d*sin, [2]=sqrt2*A/h^d*cos
__device__ float g_C[BB * TT * VV];    // 65.5 MB

__device__ __forceinline__ float frcp(float x) {
    float d;
    asm("rcp.approx.f32 %0, %1;" : "=f"(d) : "f"(x));
    return d;
}
__device__ __forceinline__ float fadd_rn(float a, float b) {   // contraction-proof
    float r;
    asm("add.rn.f32 %0, %1, %2;" : "=f"(r) : "f"(a), "f"(b));
    return r;
}

// ---------------------------------------------------------------------------
// Kernel A: per-vocab harmonic tables; sqrt(2) baked into both trig entries
// so any product of two trig entries carries the final 2.0 factor.
// ---------------------------------------------------------------------------
__global__ void build_tables(const float* __restrict__ freq,
                             const float* __restrict__ amp,
                             const float* __restrict__ decay) {
    int v = blockIdx.x * blockDim.x + threadIdx.x;
    if (v >= VV) return;
    float f   = freq[v];
    float A   = amp[v];
    float dec = decay[0];
    const float TWO_PI = 6.2831853071795864769f;
    const float SQRT2  = 1.4142135623730951f;
#pragma unroll
    for (int j = 0; j < HH; j++) {
        float h   = (float)(j + 1);
        float ang = TWO_PI * f * h;
        float Ah  = SQRT2 * A / powf(h, dec);
        float s, c;
        sincosf(ang, &s, &c);
        g_vocab[0][j][v] = ang;
        g_vocab[1][j][v] = Ah * s;
        g_vocab[2][j][v] = Ah * c;
    }
}

// ---------------------------------------------------------------------------
// Kernel B: batch-2 reciprocal fast path, collision guard hoisted to a per-ttl
// harmonic RATIO test (7 checks, fixed-lat pipes only, no per-term FMNMX):
//   collision exists  <=>  exists i: dist(x*i, Z) < tau,  x=a1/b1, tau~theta/|b1|
// Rare exact recompute per (thread,ttl) on guard fire (superset of true set).
// ---------------------------------------------------------------------------
__global__ void __launch_bounds__(256) wave_C(const int* __restrict__ ids, int b) {
    __shared__ float4 sT[16][8];      // (a, sa, ca, 0) per (ttl, i); LDS.128 broadcast
    __shared__ int    sid[16];

    const int t0  = blockIdx.y * 16;
    const int tid = threadIdx.x;

    if (tid < 16) sid[tid] = ids[b * TT + t0 + tid];
    __syncthreads();
    if (tid < 16 * HH) {                 // 112 (tt,i) pairs
        int ttl = tid / HH, i = tid % HH;
        int u   = sid[ttl];
        sT[ttl][i] = make_float4(g_vocab[0][i][u], g_vocab[1][i][u],
                                 g_vocab[2][i][u], 0.0f);
    }
    __syncthreads();

    const int v  = blockIdx.x * 256 + tid;
    const int vc = (v < VV) ? v : (VV - 1);
    const bool ok = (v < VV);

    // Per-v pair constants: jp pairs (0,1),(2,3),(4,5); scalar j=6.
    float nb0[3], nb1[3], cS1[3], cM1[3], cS2[3], cM2[3];
#pragma unroll
    for (int jp = 0; jp < 3; jp++) {
        int j0 = 2 * jp, j1 = 2 * jp + 1;
        float b0 = g_vocab[0][j0][vc], b1 = g_vocab[0][j1][vc];
        float c0 = g_vocab[2][j0][vc], c1 = g_vocab[2][j1][vc];
        float s0 = g_vocab[1][j0][vc], s1 = g_vocab[1][j1][vc];
        nb0[jp] = -b0;
        nb1[jp] = -b1;
        cS1[jp] = c0 + c1;                       // S1 (cos side)
        cM1[jp] = -fmaf(c0, b1, c1 * b0);
        cS2[jp] = -(s0 + s1);                    // S2 (neg-sin side)
        cM2[jp] = fmaf(s0, b1, s1 * b0);
    }
    const float nb6  = -g_vocab[0][6][vc];
    const float vcs6 =  g_vocab[2][6][vc];
    const float nvs6 = -g_vocab[1][6][vc];

    // Guard constants: b1_v = -nb0[0] = fundamental vocab angle.
    const float invb1 = frcp(-nb0[0]);                 // f_v=0 -> inf -> always recompute
    const float tau   = fabsf(invb1) * TAU_SCALE;

#pragma unroll 1                         // keep bodies in I$ once
    for (int ttl = 0; ttl < 16; ttl++) {
        const float a1 = sT[ttl][0].x;

        // --- ratio guard: min_i dist(x*i, Z), x = a1/b1 ---
        float x = a1 * invb1;
        float y = x;
        float m = 3.0f;
#pragma unroll
        for (int i = 0; i < HH; i++) {
            float t2 = fadd_rn(y, RMAGIC);
            float ry = fadd_rn(t2, -RMAGIC);
            m = fminf(m, fabsf(y - ry));
            y = fadd_rn(y, x);
        }

        float acc = 0.0f;
        if (m >= tau) {
            // --- fast path: no per-term guard work ---
#pragma unroll
            for (int i = 0; i < HH; i++) {
                const float4 T = sT[ttl][i];
                const float a = T.x, sa = T.y, ca = T.z;
                float S1 = 0.0f, S2 = 0.0f;
#pragma unroll
                for (int jp = 0; jp < 3; jp++) {
                    float r0 = a + nb0[jp];
                    float r1 = a + nb1[jp];
                    float p   = r0 * r1;
                    float inv = frcp(p);
                    float n1  = fmaf(a, cS1[jp], cM1[jp]);
                    float n2  = fmaf(a, cS2[jp], cM2[jp]);
                    S1 = fmaf(n1, inv, S1);
                    S2 = fmaf(n2, inv, S2);
                }
                {   // scalar j = 6
                    float r = a + nb6;
                    float d = frcp(r);
                    S1 = fmaf(vcs6, d, S1);
                    S2 = fmaf(nvs6, d, S2);
                }
                acc = fmaf(sa, S1, acc);
                acc = fmaf(ca, S2, acc);
            }
        } else {
            // --- rare exact recompute (R1-validated math; cold LDG reloads) ---
#pragma unroll 1
            for (int i = 0; i < HH; i++) {
                const float4 T = sT[ttl][i];
                const float a = T.x, sa = T.y, ca = T.z;
#pragma unroll
                for (int j = 0; j < HH; j++) {
                    float bj  = g_vocab[0][j][vc];
                    float vsj = g_vocab[1][j][vc];
                    float vcj = g_vocab[2][j][vc];
                    float r   = a - bj;
                    float d   = frcp(r);
                    float num = fmaf(sa, vcj, -(ca * vsj));  // 2AA*sin(r)
                    float val = num * d;
                    float alt = fmaf(sa, vsj, ca * vcj);     // 2AA*cos(r) ~ limit
                    acc += (fabsf(r) < GUARD_TH) ? alt : val;
                }
            }
        }
        if (ok) g_C[(size_t)((b * TT + t0 + ttl)) * VV + v] = acc;
    }
}

// ---------------------------------------------------------------------------
// Kernel C: exclusive cumsum over t per (b,v) column; 8-wide load batching
// ---------------------------------------------------------------------------
__global__ void __launch_bounds__(256) cumshift(float* __restrict__ out) {
    int idx = blockIdx.x * blockDim.x + threadIdx.x;
    if (idx >= BB * VV) return;
    int b = idx / VV;
    int v = idx - b * VV;
    const float* crow = g_C + (size_t)b * TT * VV + v;
    float*       orow = out + (size_t)b * TT * VV + v;
    float run = 0.0f;
#pragma unroll 1
    for (int t = 0; t < TT; t += 8) {
        float x[8];
#pragma unroll
        for (int k = 0; k < 8; k++) x[k] = crow[(size_t)(t + k) * VV];
#pragma unroll
        for (int k = 0; k < 8; k++) { orow[(size_t)(t + k) * VV] = run; run += x[k]; }
    }
}

// ---------------------------------------------------------------------------
extern "C" void kernel_launch(void* const* d_in, const int* in_sizes, int n_in,
                              void* d_out, int out_size) {
    const int*   ids   = (const int*)d_in[0];
    const float* freq  = (const float*)d_in[1];
    const float* amp   = (const float*)d_in[2];
    const float* decay = (const float*)d_in[3];
    // d_in[4] = chunk_size: result independent of chunking; ignored.

    build_tables<<<(VV + 255) / 256, 256>>>(freq, amp, decay);

    // 4 per-batch launches (same structure that let ncu land on wave_C)
    dim3 gridB((VV + 255) / 256, TT / 16, 1);
    for (int b = 0; b < BB; b++)
        wave_C<<<gridB, 256>>>(ids, b);

    cumshift<<<(BB * VV + 255) / 256, 256>>>((float*)d_out);
}